// round 1
// baseline (speedup 1.0000x reference)
#include <cuda_runtime.h>
#include <math.h>
#include <stdint.h>

#define TSEQ 4096
#define NH   16
#define NKV  4
#define HDIM 64
#define DIM  1024
#define QKVD 1536
#define KVOFF 1024
#define VOFF  1280

// ---------------- scratch (device globals; no cudaMalloc allowed) ----------
__device__ float g_qkv[TSEQ * QKVD];        // 25.2 MB
__device__ float g_q[NH * TSEQ * HDIM];     // 16.8 MB
__device__ float g_k[NKV * TSEQ * HDIM];    //  4.2 MB
__device__ float g_v[NKV * TSEQ * HDIM];    //  4.2 MB
__device__ float g_y[TSEQ * DIM];           // 16.8 MB

// ---------------- SGEMM: C[M,N] = A[M,K] * B[N,K]^T (both row-major) -------
// 128x128 tile, 256 threads, 8x8 per-thread register tile, K-step 16.
__global__ __launch_bounds__(256) void gemm_nt(const float* __restrict__ A,
                                               const float* __restrict__ B,
                                               float* __restrict__ C,
                                               int M, int N, int K) {
    __shared__ __align__(16) float As[16][132];
    __shared__ __align__(16) float Bs[16][132];
    const int tid = threadIdx.x;
    const int m0 = blockIdx.y * 128;
    const int n0 = blockIdx.x * 128;
    const int rm = (tid >> 4) << 3;
    const int rn = (tid & 15) << 3;
    const int lrow = tid & 127;

    // threads 0..127 load the A tile column-per-thread (transposed store,
    // conflict-free STS: lanes hit distinct rows); threads 128..255 load B.
    const float* src = (tid < 128) ? (A + (size_t)(m0 + lrow) * K)
                                   : (B + (size_t)(n0 + lrow) * K);
    float* dcol = (tid < 128) ? &As[0][lrow] : &Bs[0][lrow];

    float acc[8][8];
#pragma unroll
    for (int i = 0; i < 8; i++)
#pragma unroll
        for (int j = 0; j < 8; j++) acc[i][j] = 0.f;

    for (int k0 = 0; k0 < K; k0 += 16) {
        float4 v0 = *(const float4*)(src + k0);
        float4 v1 = *(const float4*)(src + k0 + 4);
        float4 v2 = *(const float4*)(src + k0 + 8);
        float4 v3 = *(const float4*)(src + k0 + 12);
        __syncthreads();  // previous compute done reading tiles
        dcol[0 * 132] = v0.x;  dcol[1 * 132] = v0.y;
        dcol[2 * 132] = v0.z;  dcol[3 * 132] = v0.w;
        dcol[4 * 132] = v1.x;  dcol[5 * 132] = v1.y;
        dcol[6 * 132] = v1.z;  dcol[7 * 132] = v1.w;
        dcol[8 * 132] = v2.x;  dcol[9 * 132] = v2.y;
        dcol[10 * 132] = v2.z; dcol[11 * 132] = v2.w;
        dcol[12 * 132] = v3.x; dcol[13 * 132] = v3.y;
        dcol[14 * 132] = v3.z; dcol[15 * 132] = v3.w;
        __syncthreads();
#pragma unroll
        for (int kk = 0; kk < 16; kk++) {
            float a[8], b[8];
            *(float4*)(a)     = *(const float4*)&As[kk][rm];
            *(float4*)(a + 4) = *(const float4*)&As[kk][rm + 4];
            *(float4*)(b)     = *(const float4*)&Bs[kk][rn];
            *(float4*)(b + 4) = *(const float4*)&Bs[kk][rn + 4];
#pragma unroll
            for (int i = 0; i < 8; i++)
#pragma unroll
                for (int j = 0; j < 8; j++) acc[i][j] += a[i] * b[j];
        }
    }
#pragma unroll
    for (int i = 0; i < 8; i++) {
        float4* cp = (float4*)(C + (size_t)(m0 + rm + i) * N + n0 + rn);
        cp[0] = make_float4(acc[i][0], acc[i][1], acc[i][2], acc[i][3]);
        cp[1] = make_float4(acc[i][4], acc[i][5], acc[i][6], acc[i][7]);
    }
}

// ---------------- prep: RMSNorm + RoPE + gain, split qkv into q/k/v --------
// one warp per 64-wide head row; lane L owns the rotary pair (L, L+32).
__global__ __launch_bounds__(256) void prep_kernel(const float* __restrict__ qkv,
                                                   const float* __restrict__ gain) {
    const int warp = blockIdx.x * 8 + (threadIdx.x >> 5);
    const int lane = threadIdx.x & 31;
    const int NQ = TSEQ * NH;
    const int NK = TSEQ * NKV;
    if (warp >= NQ + 2 * NK) return;

    if (warp < NQ + NK) {
        // q or k row: rmsnorm + rope
        int t, off;
        float g;
        float* dst;
        if (warp < NQ) {
            t = warp / NH;
            int h = warp % NH;
            off = h * HDIM;
            g = gain[h];
            dst = g_q + ((size_t)h * TSEQ + t) * HDIM;
        } else {
            int w = warp - NQ;
            t = w / NKV;
            int kv = w % NKV;
            off = KVOFF + kv * HDIM;
            g = 1.0f;
            dst = g_k + ((size_t)kv * TSEQ + t) * HDIM;
        }
        const float* src = qkv + (size_t)t * QKVD + off;
        float x1 = src[lane], x2 = src[lane + 32];
        float ss = x1 * x1 + x2 * x2;
        ss += __shfl_xor_sync(0xffffffffu, ss, 16);
        ss += __shfl_xor_sync(0xffffffffu, ss, 8);
        ss += __shfl_xor_sync(0xffffffffu, ss, 4);
        ss += __shfl_xor_sync(0xffffffffu, ss, 2);
        ss += __shfl_xor_sync(0xffffffffu, ss, 1);
        float r = rsqrtf(ss * (1.0f / 64.0f) + 1.1920929e-07f);
        x1 *= r; x2 *= r;
        // inv_freq in double, rounded to f32 (tracks jax f32 within ~ulp)
        float invf = (float)(1.0 / pow(10000.0, (double)lane * (1.0 / 32.0)));
        float fr = (float)t * invf;
        float s, c;
        sincosf(fr, &s, &c);
        dst[lane]      = (x1 * c + x2 * s) * g;
        dst[lane + 32] = (x2 * c - x1 * s) * g;
    } else {
        // v row: plain copy
        int w = warp - NQ - NK;
        int t = w / NKV, kv = w % NKV;
        const float* src = qkv + (size_t)t * QKVD + VOFF + kv * HDIM;
        float* dst = g_v + ((size_t)kv * TSEQ + t) * HDIM;
        dst[lane] = src[lane];
        dst[lane + 32] = src[lane + 32];
    }
}

// ---------------- flash attention, fp32, 64x64 tiles -----------------------
// CTA: (head, q-block of 64 rows), 128 threads.
// Thread (ry = tid>>3 in 0..15, cx = tid&7 in 0..7) owns
//   S rows  r = ry + 16*i (i<4)   [strided -> conflict-free LDS]
//   S cols  c = cx + 8*j  (j<8)
//   O cols  d = cx + 8*j
// smem: Qt[d][r] (64x64), Kt[d][j] stride 68 (aliased as Pt[c][r]), Vs[j][d].
#define ATTN_SMEM_FLOATS (64 * 64 + 64 * 68 + 64 * 64)
#define ATTN_SMEM_BYTES  (ATTN_SMEM_FLOATS * 4)

__global__ __launch_bounds__(128, 4) void attn_kernel() {
    extern __shared__ float sm[];
    float* Qt = sm;                    // [64][64] : Qt[d*64 + r]
    float* Kt = sm + 64 * 64;          // [64][68] : Kt[d*68 + j]; reused as Pt
    float* Vs = sm + 64 * 64 + 64 * 68;// [64][64] : Vs[j*64 + d]

    const int tid = threadIdx.x;
    const int h = blockIdx.y;
    const int qb = (int)gridDim.x - 1 - (int)blockIdx.x;  // heavy CTAs first
    const int kvh = h >> 2;
    const int ry = tid >> 3;
    const int cx = tid & 7;

    // load Q tile transposed, thread-per-row (conflict-free STS)
    if (tid < 64) {
        const float* qp = g_q + ((size_t)h * TSEQ + (size_t)qb * 64 + tid) * HDIM;
#pragma unroll
        for (int d = 0; d < 64; d += 4) {
            float4 v = *(const float4*)(qp + d);
            Qt[(d + 0) * 64 + tid] = v.x;
            Qt[(d + 1) * 64 + tid] = v.y;
            Qt[(d + 2) * 64 + tid] = v.z;
            Qt[(d + 3) * 64 + tid] = v.w;
        }
    }

    float O[4][8];
    float m[4], l[4];
#pragma unroll
    for (int i = 0; i < 4; i++) {
        m[i] = -INFINITY; l[i] = 0.f;
#pragma unroll
        for (int j = 0; j < 8; j++) O[i][j] = 0.f;
    }

    const float scale = 0.125f;  // 1/sqrt(64)

    for (int kb = 0; kb <= qb; kb++) {
        __syncthreads();  // prior iteration done reading Kt(=Pt)/Vs
        if (tid < 64) {
            // K tile transposed, thread-per-row
            const float* kp = g_k + ((size_t)kvh * TSEQ + (size_t)kb * 64 + tid) * HDIM;
#pragma unroll
            for (int d = 0; d < 64; d += 4) {
                float4 v = *(const float4*)(kp + d);
                Kt[(d + 0) * 68 + tid] = v.x;
                Kt[(d + 1) * 68 + tid] = v.y;
                Kt[(d + 2) * 68 + tid] = v.z;
                Kt[(d + 3) * 68 + tid] = v.w;
            }
        } else {
            // V tile row-major, cooperative float4 (conflict-free per phase)
            const float* vp = g_v + ((size_t)kvh * TSEQ + (size_t)kb * 64) * HDIM;
            for (int idx = tid - 64; idx < 64 * 16; idx += 64) {
                int row = idx >> 4, seg = (idx & 15) << 2;
                *(float4*)&Vs[row * 64 + seg] = *(const float4*)(vp + row * 64 + seg);
            }
        }
        __syncthreads();

        // ---- S = Q K^T ----
        float S[4][8];
#pragma unroll
        for (int i = 0; i < 4; i++)
#pragma unroll
            for (int j = 0; j < 8; j++) S[i][j] = 0.f;

#pragma unroll 4
        for (int d = 0; d < 64; d++) {
            float a0 = Qt[d * 64 + ry];
            float a1 = Qt[d * 64 + ry + 16];
            float a2 = Qt[d * 64 + ry + 32];
            float a3 = Qt[d * 64 + ry + 48];
            float b[8];
#pragma unroll
            for (int j = 0; j < 8; j++) b[j] = Kt[d * 68 + cx + 8 * j];
#pragma unroll
            for (int j = 0; j < 8; j++) {
                S[0][j] += a0 * b[j];
                S[1][j] += a1 * b[j];
                S[2][j] += a2 * b[j];
                S[3][j] += a3 * b[j];
            }
        }

        // ---- scale + causal mask ----
        if (kb == qb) {
#pragma unroll
            for (int i = 0; i < 4; i++) {
                int rg = ry + 16 * i;
#pragma unroll
                for (int j = 0; j < 8; j++) {
                    int jg = cx + 8 * j;
                    S[i][j] = (jg <= rg) ? S[i][j] * scale : -INFINITY;
                }
            }
        } else {
#pragma unroll
            for (int i = 0; i < 4; i++)
#pragma unroll
                for (int j = 0; j < 8; j++) S[i][j] *= scale;
        }

        // ---- online softmax (row stats across the 8 cx lanes) ----
#pragma unroll
        for (int i = 0; i < 4; i++) {
            float mx = S[i][0];
#pragma unroll
            for (int j = 1; j < 8; j++) mx = fmaxf(mx, S[i][j]);
            mx = fmaxf(mx, __shfl_xor_sync(0xffffffffu, mx, 1));
            mx = fmaxf(mx, __shfl_xor_sync(0xffffffffu, mx, 2));
            mx = fmaxf(mx, __shfl_xor_sync(0xffffffffu, mx, 4));
            float mn = fmaxf(m[i], mx);
            float alpha = __expf(m[i] - mn);
            m[i] = mn;
            float s = 0.f;
#pragma unroll
            for (int j = 0; j < 8; j++) {
                float p = __expf(S[i][j] - mn);
                S[i][j] = p;             // reuse S registers as P
                s += p;
            }
            s += __shfl_xor_sync(0xffffffffu, s, 1);
            s += __shfl_xor_sync(0xffffffffu, s, 2);
            s += __shfl_xor_sync(0xffffffffu, s, 4);
            l[i] = l[i] * alpha + s;
#pragma unroll
            for (int j = 0; j < 8; j++) O[i][j] *= alpha;
        }

        // ---- write P transposed into Kt region (Pt[c*68 + r]) ----
        __syncthreads();  // everyone done reading Kt as K
#pragma unroll
        for (int i = 0; i < 4; i++)
#pragma unroll
            for (int j = 0; j < 8; j++)
                Kt[(cx + 8 * j) * 68 + ry + 16 * i] = S[i][j];
        __syncwarp();     // Pt rows a thread reads were written by its own warp

        // ---- O += P V ----
#pragma unroll 4
        for (int j = 0; j < 64; j++) {
            float a0 = Kt[j * 68 + ry];
            float a1 = Kt[j * 68 + ry + 16];
            float a2 = Kt[j * 68 + ry + 32];
            float a3 = Kt[j * 68 + ry + 48];
            float b[8];
#pragma unroll
            for (int jj = 0; jj < 8; jj++) b[jj] = Vs[j * 64 + cx + 8 * jj];
#pragma unroll
            for (int jj = 0; jj < 8; jj++) {
                O[0][jj] += a0 * b[jj];
                O[1][jj] += a1 * b[jj];
                O[2][jj] += a2 * b[jj];
                O[3][jj] += a3 * b[jj];
            }
        }
    }

    // ---- epilogue: normalize, write y[t][h*64 + d] ----
#pragma unroll
    for (int i = 0; i < 4; i++) {
        float inv = 1.0f / l[i];
        int t = qb * 64 + ry + 16 * i;
        float* yp = g_y + (size_t)t * DIM + h * HDIM;
#pragma unroll
        for (int j = 0; j < 8; j++) yp[cx + 8 * j] = O[i][j] * inv;
    }
}

// ---------------- launch ---------------------------------------------------
extern "C" void kernel_launch(void* const* d_in, const int* in_sizes, int n_in,
                              void* d_out, int out_size) {
    const float* x      = (const float*)d_in[0];
    const float* w_qkv  = (const float*)d_in[1];
    const float* w_proj = (const float*)d_in[2];
    const float* q_gain = (const float*)d_in[3];
    float* out = (float*)d_out;

    float *qkv_p, *y_p;
    cudaGetSymbolAddress((void**)&qkv_p, g_qkv);
    cudaGetSymbolAddress((void**)&y_p, g_y);

    // qkv = x @ w_qkv^T : [4096,1536]
    gemm_nt<<<dim3(QKVD / 128, TSEQ / 128), 256>>>(x, w_qkv, qkv_p, TSEQ, QKVD, DIM);

    // rmsnorm + rope + gain + split
    {
        int nwarps = TSEQ * (NH + 2 * NKV);
        prep_kernel<<<nwarps / 8, 256>>>(qkv_p, q_gain);
    }

    // flash attention
    cudaFuncSetAttribute(attn_kernel, cudaFuncAttributeMaxDynamicSharedMemorySize,
                         ATTN_SMEM_BYTES);
    attn_kernel<<<dim3(TSEQ / 64, NH), 128, ATTN_SMEM_BYTES>>>();

    // out = y @ w_proj^T : [4096,1024]
    gemm_nt<<<dim3(DIM / 128, TSEQ / 128), 256>>>(y_p, w_proj, out, TSEQ, DIM, DIM);
}

// round 2
// speedup vs baseline: 1.9301x; 1.9301x over previous
#include <cuda_runtime.h>
#include <math.h>
#include <stdint.h>

#define TSEQ 4096
#define NH   16
#define NKV  4
#define HDIM 64
#define DIM  1024
#define QKVD 1536
#define KVOFF 1024
#define VOFF  1280

// ---------------- scratch (device globals; no cudaMalloc allowed) ----------
__device__ float g_qkv[TSEQ * QKVD];
__device__ float g_q[NH * TSEQ * HDIM];
__device__ float g_k[NKV * TSEQ * HDIM];
__device__ float g_v[NKV * TSEQ * HDIM];
__device__ float g_y[TSEQ * DIM];

// ---------------- tf32 helpers ---------------------------------------------
__device__ __forceinline__ uint32_t f2tf(float f) {
    uint32_t u;
    asm("cvt.rna.tf32.f32 %0, %1;" : "=r"(u) : "f"(f));
    return u;
}

__device__ __forceinline__ void mma_tf32(float c[4], const uint32_t a[4],
                                         const uint32_t b[2]) {
    asm volatile(
        "mma.sync.aligned.m16n8k8.row.col.f32.tf32.tf32.f32 "
        "{%0,%1,%2,%3}, {%4,%5,%6,%7}, {%8,%9}, {%0,%1,%2,%3};"
        : "+f"(c[0]), "+f"(c[1]), "+f"(c[2]), "+f"(c[3])
        : "r"(a[0]), "r"(a[1]), "r"(a[2]), "r"(a[3]), "r"(b[0]), "r"(b[1]));
}

__device__ __forceinline__ void cp16(void* smem_dst, const void* gsrc) {
    uint32_t s = (uint32_t)__cvta_generic_to_shared(smem_dst);
    asm volatile("cp.async.ca.shared.global [%0], [%1], 16;" :: "r"(s), "l"(gsrc));
}
__device__ __forceinline__ void cp_commit_wait0() {
    asm volatile("cp.async.commit_group;");
    asm volatile("cp.async.wait_group 0;");
}

// ---------------- tf32 GEMM: C[M,N] = A[M,K] * B[N,K]^T --------------------
// 128x128 tile, 256 threads = 8 warps (2m x 4n), warp tile 64x32.
// smem [k][m] / [k][n], stride 136 (136 % 32 == 8 -> conflict-free frags).
__global__ __launch_bounds__(256, 2) void gemm_tf32(const float* __restrict__ A,
                                                    const float* __restrict__ B,
                                                    float* __restrict__ C,
                                                    int M, int N, int K) {
    __shared__ __align__(16) uint32_t As[16][136];
    __shared__ __align__(16) uint32_t Bs[16][136];
    const int tid = threadIdx.x;
    const int m0 = blockIdx.y * 128;
    const int n0 = blockIdx.x * 128;
    const int warp = tid >> 5;
    const int lane = tid & 31;
    const int gid = lane >> 2;
    const int tig = lane & 3;
    const int wm = (warp & 1) * 64;
    const int wn = (warp >> 1) * 32;
    const int lrow = tid & 127;

    const float* src = (tid < 128) ? (A + (size_t)(m0 + lrow) * K)
                                   : (B + (size_t)(n0 + lrow) * K);
    uint32_t* dcol = (tid < 128) ? &As[0][lrow] : &Bs[0][lrow];

    float acc[4][4][4];
#pragma unroll
    for (int mi = 0; mi < 4; mi++)
#pragma unroll
        for (int ni = 0; ni < 4; ni++)
#pragma unroll
            for (int f = 0; f < 4; f++) acc[mi][ni][f] = 0.f;

    float4 v0 = *(const float4*)(src + 0);
    float4 v1 = *(const float4*)(src + 4);
    float4 v2 = *(const float4*)(src + 8);
    float4 v3 = *(const float4*)(src + 12);

    for (int k0 = 0; k0 < K; k0 += 16) {
        __syncthreads();
        dcol[0 * 136] = f2tf(v0.x);  dcol[1 * 136] = f2tf(v0.y);
        dcol[2 * 136] = f2tf(v0.z);  dcol[3 * 136] = f2tf(v0.w);
        dcol[4 * 136] = f2tf(v1.x);  dcol[5 * 136] = f2tf(v1.y);
        dcol[6 * 136] = f2tf(v1.z);  dcol[7 * 136] = f2tf(v1.w);
        dcol[8 * 136] = f2tf(v2.x);  dcol[9 * 136] = f2tf(v2.y);
        dcol[10 * 136] = f2tf(v2.z); dcol[11 * 136] = f2tf(v2.w);
        dcol[12 * 136] = f2tf(v3.x); dcol[13 * 136] = f2tf(v3.y);
        dcol[14 * 136] = f2tf(v3.z); dcol[15 * 136] = f2tf(v3.w);
        __syncthreads();
        if (k0 + 16 < K) {
            v0 = *(const float4*)(src + k0 + 16);
            v1 = *(const float4*)(src + k0 + 20);
            v2 = *(const float4*)(src + k0 + 24);
            v3 = *(const float4*)(src + k0 + 28);
        }
#pragma unroll
        for (int ks = 0; ks < 16; ks += 8) {
            uint32_t af[4][4], bf[4][2];
#pragma unroll
            for (int mi = 0; mi < 4; mi++) {
                af[mi][0] = As[ks + tig][wm + 16 * mi + gid];
                af[mi][1] = As[ks + tig][wm + 16 * mi + gid + 8];
                af[mi][2] = As[ks + tig + 4][wm + 16 * mi + gid];
                af[mi][3] = As[ks + tig + 4][wm + 16 * mi + gid + 8];
            }
#pragma unroll
            for (int ni = 0; ni < 4; ni++) {
                bf[ni][0] = Bs[ks + tig][wn + 8 * ni + gid];
                bf[ni][1] = Bs[ks + tig + 4][wn + 8 * ni + gid];
            }
#pragma unroll
            for (int mi = 0; mi < 4; mi++)
#pragma unroll
                for (int ni = 0; ni < 4; ni++) mma_tf32(acc[mi][ni], af[mi], bf[ni]);
        }
    }

#pragma unroll
    for (int mi = 0; mi < 4; mi++) {
        int r0 = m0 + wm + 16 * mi + gid;
#pragma unroll
        for (int ni = 0; ni < 4; ni++) {
            int c = n0 + wn + 8 * ni + 2 * tig;
            *(float2*)(C + (size_t)r0 * N + c) = make_float2(acc[mi][ni][0], acc[mi][ni][1]);
            *(float2*)(C + (size_t)(r0 + 8) * N + c) = make_float2(acc[mi][ni][2], acc[mi][ni][3]);
        }
    }
}

// ---------------- prep: RMSNorm + RoPE + gain, split qkv -------------------
__global__ __launch_bounds__(256) void prep_kernel(const float* __restrict__ qkv,
                                                   const float* __restrict__ gain) {
    const int warp = blockIdx.x * 8 + (threadIdx.x >> 5);
    const int lane = threadIdx.x & 31;
    const int NQ = TSEQ * NH;
    const int NK = TSEQ * NKV;
    if (warp >= NQ + 2 * NK) return;

    if (warp < NQ + NK) {
        int t, off;
        float g;
        float* dst;
        if (warp < NQ) {
            t = warp / NH;
            int h = warp % NH;
            off = h * HDIM;
            g = gain[h];
            dst = g_q + ((size_t)h * TSEQ + t) * HDIM;
        } else {
            int w = warp - NQ;
            t = w / NKV;
            int kv = w % NKV;
            off = KVOFF + kv * HDIM;
            g = 1.0f;
            dst = g_k + ((size_t)kv * TSEQ + t) * HDIM;
        }
        const float* src = qkv + (size_t)t * QKVD + off;
        float x1 = src[lane], x2 = src[lane + 32];
        float ss = x1 * x1 + x2 * x2;
        ss += __shfl_xor_sync(0xffffffffu, ss, 16);
        ss += __shfl_xor_sync(0xffffffffu, ss, 8);
        ss += __shfl_xor_sync(0xffffffffu, ss, 4);
        ss += __shfl_xor_sync(0xffffffffu, ss, 2);
        ss += __shfl_xor_sync(0xffffffffu, ss, 1);
        float r = rsqrtf(ss * (1.0f / 64.0f) + 1.1920929e-07f);
        x1 *= r; x2 *= r;
        float invf = (float)(1.0 / pow(10000.0, (double)lane * (1.0 / 32.0)));
        float fr = (float)t * invf;
        float s, c;
        sincosf(fr, &s, &c);
        dst[lane]      = (x1 * c + x2 * s) * g;
        dst[lane + 32] = (x2 * c - x1 * s) * g;
    } else {
        int w = warp - NQ - NK;
        int t = w / NKV, kv = w % NKV;
        const float* src = qkv + (size_t)t * QKVD + VOFF + kv * HDIM;
        float* dst = g_v + ((size_t)kv * TSEQ + t) * HDIM;
        dst[lane] = src[lane];
        dst[lane + 32] = src[lane + 32];
    }
}

// ---------------- flash attention, tf32 mma, 64x64 tiles -------------------
// 128 threads = 4 warps; warp w owns q-rows [16w, 16w+16).
// smem (u32 elems): Qs[64][68] tf32 | Ks[64][68] f32->tf32 (aliased as Ps) |
//                   Vs[64][72] f32.
#define QS_STRIDE 68
#define VS_STRIDE 72
#define ATTN_SMEM_U32 (64 * QS_STRIDE * 2 + 64 * VS_STRIDE)
#define ATTN_SMEM_BYTES (ATTN_SMEM_U32 * 4)

__global__ __launch_bounds__(128, 4) void attn_kernel() {
    extern __shared__ __align__(16) uint32_t smu[];
    uint32_t* Qs = smu;                       // [64][68] tf32
    uint32_t* Ks = smu + 64 * QS_STRIDE;      // [64][68]; aliased as Ps
    uint32_t* Vs = smu + 2 * 64 * QS_STRIDE;  // [64][72]

    const int tid = threadIdx.x;
    const int h = blockIdx.y;
    const int qb = (int)gridDim.x - 1 - (int)blockIdx.x;  // heavy CTAs first
    const int kvh = h >> 2;
    const int lane = tid & 31;
    const int warp = tid >> 5;
    const int gid = lane >> 2;
    const int tig = lane & 3;
    const int q0w = warp * 16;

    // ---- load Q tile (row-major [q][d]), cvt to tf32 ----
    {
        const float* qbase = g_q + ((size_t)h * TSEQ + (size_t)qb * 64) * HDIM;
#pragma unroll
        for (int s = 0; s < 8; s++) {
            int slot = tid + s * 128;
            int row = slot >> 4, c4 = (slot & 15) << 2;
            float4 v = *(const float4*)(qbase + row * HDIM + c4);
            uint32_t* d = &Qs[row * QS_STRIDE + c4];
            d[0] = f2tf(v.x); d[1] = f2tf(v.y); d[2] = f2tf(v.z); d[3] = f2tf(v.w);
        }
    }

    float of[8][4];
    float m0 = -INFINITY, m1 = -INFINITY, l0 = 0.f, l1 = 0.f;
#pragma unroll
    for (int ni = 0; ni < 8; ni++)
#pragma unroll
        for (int f = 0; f < 4; f++) of[ni][f] = 0.f;

    const float scale = 0.125f;

    for (int kb = 0; kb <= qb; kb++) {
        __syncthreads();  // prev iter done reading Ks(=Ps)/Vs (and Q store done)

        // ---- async load K,V tiles (f32) ----
        const float* kbase = g_k + ((size_t)kvh * TSEQ + (size_t)kb * 64) * HDIM;
        const float* vbase = g_v + ((size_t)kvh * TSEQ + (size_t)kb * 64) * HDIM;
#pragma unroll
        for (int s = 0; s < 8; s++) {
            int slot = tid + s * 128;
            int row = slot >> 4, c4 = (slot & 15) << 2;
            cp16(&Ks[row * QS_STRIDE + c4], kbase + row * HDIM + c4);
            cp16(&Vs[row * VS_STRIDE + c4], vbase + row * HDIM + c4);
        }
        cp_commit_wait0();
        // in-place cvt of own slots (own cp.asyncs are complete)
#pragma unroll
        for (int s = 0; s < 8; s++) {
            int slot = tid + s * 128;
            int row = slot >> 4, c4 = (slot & 15) << 2;
            {
                float4 v = *reinterpret_cast<float4*>(&Ks[row * QS_STRIDE + c4]);
                uint32_t* d = &Ks[row * QS_STRIDE + c4];
                d[0] = f2tf(v.x); d[1] = f2tf(v.y); d[2] = f2tf(v.z); d[3] = f2tf(v.w);
            }
            {
                float4 v = *reinterpret_cast<float4*>(&Vs[row * VS_STRIDE + c4]);
                uint32_t* d = &Vs[row * VS_STRIDE + c4];
                d[0] = f2tf(v.x); d[1] = f2tf(v.y); d[2] = f2tf(v.z); d[3] = f2tf(v.w);
            }
        }
        __syncthreads();

        // ---- S = Q K^T : 8 k-steps over d, 8 n-tiles over kc ----
        float sf[8][4];
#pragma unroll
        for (int ni = 0; ni < 8; ni++)
#pragma unroll
            for (int f = 0; f < 4; f++) sf[ni][f] = 0.f;

#pragma unroll
        for (int ks = 0; ks < 64; ks += 8) {
            uint32_t a[4];
            a[0] = Qs[(q0w + gid) * QS_STRIDE + ks + tig];
            a[1] = Qs[(q0w + gid + 8) * QS_STRIDE + ks + tig];
            a[2] = Qs[(q0w + gid) * QS_STRIDE + ks + tig + 4];
            a[3] = Qs[(q0w + gid + 8) * QS_STRIDE + ks + tig + 4];
#pragma unroll
            for (int ni = 0; ni < 8; ni++) {
                uint32_t b[2];
                b[0] = Ks[(8 * ni + gid) * QS_STRIDE + ks + tig];
                b[1] = Ks[(8 * ni + gid) * QS_STRIDE + ks + tig + 4];
                mma_tf32(sf[ni], a, b);
            }
        }

        // ---- scale + causal mask ----
        if (kb == qb) {
            int r0 = q0w + gid, r1 = r0 + 8;
#pragma unroll
            for (int ni = 0; ni < 8; ni++) {
                int c0 = 8 * ni + 2 * tig, c1 = c0 + 1;
                sf[ni][0] = (c0 <= r0) ? sf[ni][0] * scale : -INFINITY;
                sf[ni][1] = (c1 <= r0) ? sf[ni][1] * scale : -INFINITY;
                sf[ni][2] = (c0 <= r1) ? sf[ni][2] * scale : -INFINITY;
                sf[ni][3] = (c1 <= r1) ? sf[ni][3] * scale : -INFINITY;
            }
        } else {
#pragma unroll
            for (int ni = 0; ni < 8; ni++)
#pragma unroll
                for (int f = 0; f < 4; f++) sf[ni][f] *= scale;
        }

        // ---- online softmax (rows gid / gid+8; reduce over quad lanes) ----
        float mx0 = -INFINITY, mx1 = -INFINITY;
#pragma unroll
        for (int ni = 0; ni < 8; ni++) {
            mx0 = fmaxf(mx0, fmaxf(sf[ni][0], sf[ni][1]));
            mx1 = fmaxf(mx1, fmaxf(sf[ni][2], sf[ni][3]));
        }
        mx0 = fmaxf(mx0, __shfl_xor_sync(0xffffffffu, mx0, 1));
        mx0 = fmaxf(mx0, __shfl_xor_sync(0xffffffffu, mx0, 2));
        mx1 = fmaxf(mx1, __shfl_xor_sync(0xffffffffu, mx1, 1));
        mx1 = fmaxf(mx1, __shfl_xor_sync(0xffffffffu, mx1, 2));
        float mn0 = fmaxf(m0, mx0), mn1 = fmaxf(m1, mx1);
        float alpha0 = __expf(m0 - mn0), alpha1 = __expf(m1 - mn1);
        m0 = mn0; m1 = mn1;
        float s0 = 0.f, s1 = 0.f;
#pragma unroll
        for (int ni = 0; ni < 8; ni++) {
            sf[ni][0] = __expf(sf[ni][0] - mn0); s0 += sf[ni][0];
            sf[ni][1] = __expf(sf[ni][1] - mn0); s0 += sf[ni][1];
            sf[ni][2] = __expf(sf[ni][2] - mn1); s1 += sf[ni][2];
            sf[ni][3] = __expf(sf[ni][3] - mn1); s1 += sf[ni][3];
        }
        s0 += __shfl_xor_sync(0xffffffffu, s0, 1);
        s0 += __shfl_xor_sync(0xffffffffu, s0, 2);
        s1 += __shfl_xor_sync(0xffffffffu, s1, 1);
        s1 += __shfl_xor_sync(0xffffffffu, s1, 2);
        l0 = l0 * alpha0 + s0;
        l1 = l1 * alpha1 + s1;
#pragma unroll
        for (int ni = 0; ni < 8; ni++) {
            of[ni][0] *= alpha0; of[ni][1] *= alpha0;
            of[ni][2] *= alpha1; of[ni][3] *= alpha1;
        }

        // ---- write P (tf32) into Ks region; own-warp rows only ----
        __syncthreads();  // all warps done reading Ks as K
        uint32_t* Ps = Ks;
#pragma unroll
        for (int ni = 0; ni < 8; ni++) {
            int c = 8 * ni + 2 * tig;
            *(uint2*)&Ps[(q0w + gid) * QS_STRIDE + c] =
                make_uint2(f2tf(sf[ni][0]), f2tf(sf[ni][1]));
            *(uint2*)&Ps[(q0w + gid + 8) * QS_STRIDE + c] =
                make_uint2(f2tf(sf[ni][2]), f2tf(sf[ni][3]));
        }
        __syncwarp();

        // ---- O += P V : k over kc, n over d ----
#pragma unroll
        for (int ks = 0; ks < 64; ks += 8) {
            uint32_t a[4];
            a[0] = Ps[(q0w + gid) * QS_STRIDE + ks + tig];
            a[1] = Ps[(q0w + gid + 8) * QS_STRIDE + ks + tig];
            a[2] = Ps[(q0w + gid) * QS_STRIDE + ks + tig + 4];
            a[3] = Ps[(q0w + gid + 8) * QS_STRIDE + ks + tig + 4];
#pragma unroll
            for (int ni = 0; ni < 8; ni++) {
                uint32_t b[2];
                b[0] = Vs[(ks + tig) * VS_STRIDE + 8 * ni + gid];
                b[1] = Vs[(ks + tig + 4) * VS_STRIDE + 8 * ni + gid];
                mma_tf32(of[ni], a, b);
            }
        }
    }

    // ---- epilogue ----
    float inv0 = 1.0f / l0, inv1 = 1.0f / l1;
    int t0 = qb * 64 + q0w + gid;
    float* ybase = g_y + (size_t)t0 * DIM + h * HDIM;
#pragma unroll
    for (int ni = 0; ni < 8; ni++) {
        int c = 8 * ni + 2 * tig;
        *(float2*)(ybase + c) = make_float2(of[ni][0] * inv0, of[ni][1] * inv0);
        *(float2*)(ybase + 8 * DIM + c) = make_float2(of[ni][2] * inv1, of[ni][3] * inv1);
    }
}

// ---------------- launch ---------------------------------------------------
extern "C" void kernel_launch(void* const* d_in, const int* in_sizes, int n_in,
                              void* d_out, int out_size) {
    const float* x      = (const float*)d_in[0];
    const float* w_qkv  = (const float*)d_in[1];
    const float* w_proj = (const float*)d_in[2];
    const float* q_gain = (const float*)d_in[3];
    float* out = (float*)d_out;

    float *qkv_p, *y_p;
    cudaGetSymbolAddress((void**)&qkv_p, g_qkv);
    cudaGetSymbolAddress((void**)&y_p, g_y);

    gemm_tf32<<<dim3(QKVD / 128, TSEQ / 128), 256>>>(x, w_qkv, qkv_p, TSEQ, QKVD, DIM);

    {
        int nwarps = TSEQ * (NH + 2 * NKV);
        prep_kernel<<<nwarps / 8, 256>>>(qkv_p, q_gain);
    }

    cudaFuncSetAttribute(attn_kernel, cudaFuncAttributeMaxDynamicSharedMemorySize,
                         ATTN_SMEM_BYTES);
    attn_kernel<<<dim3(TSEQ / 64, NH), 128, ATTN_SMEM_BYTES>>>();

    gemm_tf32<<<dim3(DIM / 128, TSEQ / 128), 256>>>(y_p, w_proj, out, TSEQ, DIM, DIM);
}

// round 3
// speedup vs baseline: 2.3157x; 1.1998x over previous
#include <cuda_runtime.h>
#include <math.h>
#include <stdint.h>

#define TSEQ 4096
#define NH   16
#define NKV  4
#define HDIM 64
#define DIM  1024
#define QKVD 1536
#define KVOFF 1024
#define VOFF  1280

// ---------------- scratch (device globals; no cudaMalloc allowed) ----------
__device__ float g_qkv[TSEQ * QKVD];
__device__ float g_q[NH * TSEQ * HDIM];
__device__ float g_k[NKV * TSEQ * HDIM];
__device__ float g_v[NKV * TSEQ * HDIM];
__device__ float g_y[TSEQ * DIM];
__device__ float g_xr[TSEQ * DIM];       // pre-rounded copies (tf32-in-f32)
__device__ float g_wq[QKVD * DIM];
__device__ float g_wp[DIM * DIM];

// ---------------- tf32 helpers ---------------------------------------------
__device__ __forceinline__ uint32_t f2tf(float f) {
    uint32_t u;
    asm("cvt.rna.tf32.f32 %0, %1;" : "=r"(u) : "f"(f));
    return u;
}

__device__ __forceinline__ void mma_tf32(float c[4], const uint32_t a[4],
                                         const uint32_t b[2]) {
    asm volatile(
        "mma.sync.aligned.m16n8k8.row.col.f32.tf32.tf32.f32 "
        "{%0,%1,%2,%3}, {%4,%5,%6,%7}, {%8,%9}, {%0,%1,%2,%3};"
        : "+f"(c[0]), "+f"(c[1]), "+f"(c[2]), "+f"(c[3])
        : "r"(a[0]), "r"(a[1]), "r"(a[2]), "r"(a[3]), "r"(b[0]), "r"(b[1]));
}

__device__ __forceinline__ void cp16(void* smem_dst, const void* gsrc) {
    uint32_t s = (uint32_t)__cvta_generic_to_shared(smem_dst);
    asm volatile("cp.async.ca.shared.global [%0], [%1], 16;" :: "r"(s), "l"(gsrc));
}

// ---------------- pre-round pass: f32 -> tf32-rounded f32 ------------------
__global__ __launch_bounds__(256) void round_kernel(const float* __restrict__ src,
                                                    float* __restrict__ dst, int n4) {
    int i = blockIdx.x * blockDim.x + threadIdx.x;
    for (; i < n4; i += gridDim.x * blockDim.x) {
        float4 v = ((const float4*)src)[i];
        uint4 u = make_uint4(f2tf(v.x), f2tf(v.y), f2tf(v.z), f2tf(v.w));
        ((uint4*)dst)[i] = u;
    }
}

// ---------------- tf32 GEMM: C[M,N] = A[M,K] * B[N,K]^T --------------------
// inputs pre-rounded. 128x128 tile, 8 warps (2m x 4n), warp tile 64x32.
// 3-stage cp.async pipeline. smem row stride 20 u32 (conflict-free frags).
#define GS 20
#define GSTG (128 * GS)          // per-tensor per-stage u32
#define GEMM_SMEM_BYTES (3 * 2 * GSTG * 4)

__global__ __launch_bounds__(256, 2) void gemm_tf32(const float* __restrict__ A,
                                                    const float* __restrict__ B,
                                                    float* __restrict__ C,
                                                    int M, int N, int K) {
    extern __shared__ __align__(16) uint32_t gsm[];
    const int tid = threadIdx.x;
    const int m0 = blockIdx.y * 128;
    const int n0 = blockIdx.x * 128;
    const int warp = tid >> 5;
    const int lane = tid & 31;
    const int gid = lane >> 2;
    const int tig = lane & 3;
    const int wm = (warp & 1) * 64;
    const int wn = (warp >> 1) * 32;

    auto issue = [&](int k0, int s) {
        uint32_t* As = gsm + s * 2 * GSTG;
        uint32_t* Bs = As + GSTG;
#pragma unroll
        for (int i = 0; i < 4; i++) {
            int id = tid + 256 * i;       // 0..1023
            int rid = id & 511;
            int row = rid >> 2, c4 = (rid & 3) << 2;
            const float* src = (id < 512)
                ? A + (size_t)(m0 + row) * K + k0 + c4
                : B + (size_t)(n0 + row) * K + k0 + c4;
            uint32_t* dst = ((id < 512) ? As : Bs) + row * GS + c4;
            cp16(dst, src);
        }
        asm volatile("cp.async.commit_group;");
    };

    float acc[4][4][4];
#pragma unroll
    for (int mi = 0; mi < 4; mi++)
#pragma unroll
        for (int ni = 0; ni < 4; ni++)
#pragma unroll
            for (int f = 0; f < 4; f++) acc[mi][ni][f] = 0.f;

    const int nIter = K / 16;
    issue(0, 0);
    issue(16, 1);

    for (int it = 0; it < nIter; it++) {
        asm volatile("cp.async.wait_group 1;");
        __syncthreads();
        if (it + 2 < nIter) issue((it + 2) * 16, (it + 2) % 3);
        else asm volatile("cp.async.commit_group;");

        const uint32_t* As = gsm + (it % 3) * 2 * GSTG;
        const uint32_t* Bs = As + GSTG;
#pragma unroll
        for (int ks = 0; ks < 16; ks += 8) {
            uint32_t af[4][4], bf[4][2];
#pragma unroll
            for (int mi = 0; mi < 4; mi++) {
                int r = (wm + 16 * mi + gid) * GS + ks + tig;
                af[mi][0] = As[r];
                af[mi][1] = As[r + 8 * GS];
                af[mi][2] = As[r + 4];
                af[mi][3] = As[r + 8 * GS + 4];
            }
#pragma unroll
            for (int ni = 0; ni < 4; ni++) {
                int r = (wn + 8 * ni + gid) * GS + ks + tig;
                bf[ni][0] = Bs[r];
                bf[ni][1] = Bs[r + 4];
            }
#pragma unroll
            for (int mi = 0; mi < 4; mi++)
#pragma unroll
                for (int ni = 0; ni < 4; ni++) mma_tf32(acc[mi][ni], af[mi], bf[ni]);
        }
    }

#pragma unroll
    for (int mi = 0; mi < 4; mi++) {
        int r0 = m0 + wm + 16 * mi + gid;
#pragma unroll
        for (int ni = 0; ni < 4; ni++) {
            int c = n0 + wn + 8 * ni + 2 * tig;
            *(float2*)(C + (size_t)r0 * N + c) = make_float2(acc[mi][ni][0], acc[mi][ni][1]);
            *(float2*)(C + (size_t)(r0 + 8) * N + c) = make_float2(acc[mi][ni][2], acc[mi][ni][3]);
        }
    }
}

// ---------------- prep: RMSNorm + RoPE + gain, outputs tf32-rounded --------
__global__ __launch_bounds__(256) void prep_kernel(const float* __restrict__ qkv,
                                                   const float* __restrict__ gain) {
    const int warp = blockIdx.x * 8 + (threadIdx.x >> 5);
    const int lane = threadIdx.x & 31;
    const int NQ = TSEQ * NH;
    const int NK = TSEQ * NKV;
    if (warp >= NQ + 2 * NK) return;

    if (warp < NQ + NK) {
        int t, off;
        float g;
        float* dst;
        if (warp < NQ) {
            t = warp / NH;
            int h = warp % NH;
            off = h * HDIM;
            g = gain[h];
            dst = g_q + ((size_t)h * TSEQ + t) * HDIM;
        } else {
            int w = warp - NQ;
            t = w / NKV;
            int kv = w % NKV;
            off = KVOFF + kv * HDIM;
            g = 1.0f;
            dst = g_k + ((size_t)kv * TSEQ + t) * HDIM;
        }
        const float* src = qkv + (size_t)t * QKVD + off;
        float x1 = src[lane], x2 = src[lane + 32];
        float ss = x1 * x1 + x2 * x2;
        ss += __shfl_xor_sync(0xffffffffu, ss, 16);
        ss += __shfl_xor_sync(0xffffffffu, ss, 8);
        ss += __shfl_xor_sync(0xffffffffu, ss, 4);
        ss += __shfl_xor_sync(0xffffffffu, ss, 2);
        ss += __shfl_xor_sync(0xffffffffu, ss, 1);
        float r = rsqrtf(ss * (1.0f / 64.0f) + 1.1920929e-07f);
        x1 *= r; x2 *= r;
        float invf = (float)(1.0 / pow(10000.0, (double)lane * (1.0 / 32.0)));
        float fr = (float)t * invf;
        float s, c;
        sincosf(fr, &s, &c);
        dst[lane]      = __uint_as_float(f2tf((x1 * c + x2 * s) * g));
        dst[lane + 32] = __uint_as_float(f2tf((x2 * c - x1 * s) * g));
    } else {
        int w = warp - NQ - NK;
        int t = w / NKV, kv = w % NKV;
        const float* src = qkv + (size_t)t * QKVD + VOFF + kv * HDIM;
        float* dst = g_v + ((size_t)kv * TSEQ + t) * HDIM;
        dst[lane] = __uint_as_float(f2tf(src[lane]));
        dst[lane + 32] = __uint_as_float(f2tf(src[lane + 32]));
    }
}

// ---------------- flash attention: 128-row Q tile, 8 warps -----------------
// Q fragments in registers; K/V double-buffered cp.async; P in own region.
// K stride 68, V stride 72, P stride 68 (all conflict-free for frag LDS).
#define KSR 68
#define VSR 72
#define ATTN_SMEM_U32 (2 * 64 * KSR + 2 * 64 * VSR + 128 * KSR)
#define ATTN_SMEM_BYTES (ATTN_SMEM_U32 * 4)

__global__ __launch_bounds__(256, 2) void attn_kernel() {
    extern __shared__ __align__(16) uint32_t smu[];
    uint32_t* Kb = smu;                           // [2][64][68]
    uint32_t* Vb = smu + 2 * 64 * KSR;            // [2][64][72]
    uint32_t* Ps = smu + 2 * 64 * KSR + 2 * 64 * VSR;  // [128][68]

    const int tid = threadIdx.x;
    const int h = blockIdx.y;
    const int qb = (int)gridDim.x - 1 - (int)blockIdx.x;  // heavy CTAs first
    const int kvh = h >> 2;
    const int lane = tid & 31;
    const int warp = tid >> 5;
    const int gid = lane >> 2;
    const int tig = lane & 3;
    const int q0w = warp * 16;
    const int kbmax = 2 * qb + 1;

    const float* kbase = g_k + ((size_t)kvh * TSEQ) * HDIM;
    const float* vbase = g_v + ((size_t)kvh * TSEQ) * HDIM;

    auto issueKV = [&](int kb) {
        const float* kp = kbase + (size_t)kb * 64 * HDIM;
        const float* vp = vbase + (size_t)kb * 64 * HDIM;
        uint32_t* Kd = Kb + (kb & 1) * 64 * KSR;
        uint32_t* Vd = Vb + (kb & 1) * 64 * VSR;
#pragma unroll
        for (int i = 0; i < 4; i++) {
            int slot = tid + 256 * i;       // 0..1023 = 64 rows x 16 chunks
            int row = slot >> 4, c4 = (slot & 15) << 2;
            cp16(Kd + row * KSR + c4, kp + row * HDIM + c4);
            cp16(Vd + row * VSR + c4, vp + row * HDIM + c4);
        }
        asm volatile("cp.async.commit_group;");
    };

    issueKV(0);

    // ---- stage Q tile through Ps (coalesced), then frags -> registers ----
    {
        const float* qp = g_q + ((size_t)h * TSEQ + (size_t)qb * 128) * HDIM;
#pragma unroll
        for (int i = 0; i < 8; i++) {
            int slot = tid + 256 * i;       // 0..2047 = 128 rows x 16 chunks
            int row = slot >> 4, c4 = (slot & 15) << 2;
            *(float4*)&Ps[row * KSR + c4] = *(const float4*)(qp + row * HDIM + c4);
        }
    }
    __syncthreads();
    uint32_t Qf[8][4];
#pragma unroll
    for (int ks = 0; ks < 8; ks++) {
        int r = (q0w + gid) * KSR + 8 * ks + tig;
        Qf[ks][0] = Ps[r];
        Qf[ks][1] = Ps[r + 8 * KSR];
        Qf[ks][2] = Ps[r + 4];
        Qf[ks][3] = Ps[r + 8 * KSR + 4];
    }

    float of[8][4];
    float m0 = -INFINITY, m1 = -INFINITY, l0 = 0.f, l1 = 0.f;
#pragma unroll
    for (int ni = 0; ni < 8; ni++)
#pragma unroll
        for (int f = 0; f < 4; f++) of[ni][f] = 0.f;

    const float scale = 0.125f;
    const int r0g = qb * 128 + q0w + gid;
    const int r1g = r0g + 8;

    for (int kb = 0; kb <= kbmax; kb++) {
        asm volatile("cp.async.wait_group 0;");
        __syncthreads();   // KV[cur] visible to all; prev iter fully done
        if (kb < kbmax) issueKV(kb + 1);

        const uint32_t* Kc = Kb + (kb & 1) * 64 * KSR;
        const uint32_t* Vc = Vb + (kb & 1) * 64 * VSR;

        // ---- S = Q K^T ----
        float sf[8][4];
#pragma unroll
        for (int ni = 0; ni < 8; ni++)
#pragma unroll
            for (int f = 0; f < 4; f++) sf[ni][f] = 0.f;

#pragma unroll
        for (int ks = 0; ks < 8; ks++) {
#pragma unroll
            for (int ni = 0; ni < 8; ni++) {
                uint32_t b[2];
                int r = (8 * ni + gid) * KSR + 8 * ks + tig;
                b[0] = Kc[r];
                b[1] = Kc[r + 4];
                mma_tf32(sf[ni], Qf[ks], b);
            }
        }

        // ---- scale + causal mask (only possibly-diagonal tiles) ----
        if (kb >= 2 * qb) {
#pragma unroll
            for (int ni = 0; ni < 8; ni++) {
                int c0 = kb * 64 + 8 * ni + 2 * tig, c1 = c0 + 1;
                sf[ni][0] = (c0 <= r0g) ? sf[ni][0] * scale : -INFINITY;
                sf[ni][1] = (c1 <= r0g) ? sf[ni][1] * scale : -INFINITY;
                sf[ni][2] = (c0 <= r1g) ? sf[ni][2] * scale : -INFINITY;
                sf[ni][3] = (c1 <= r1g) ? sf[ni][3] * scale : -INFINITY;
            }
        } else {
#pragma unroll
            for (int ni = 0; ni < 8; ni++)
#pragma unroll
                for (int f = 0; f < 4; f++) sf[ni][f] *= scale;
        }

        // ---- online softmax ----
        float mx0 = -INFINITY, mx1 = -INFINITY;
#pragma unroll
        for (int ni = 0; ni < 8; ni++) {
            mx0 = fmaxf(mx0, fmaxf(sf[ni][0], sf[ni][1]));
            mx1 = fmaxf(mx1, fmaxf(sf[ni][2], sf[ni][3]));
        }
        mx0 = fmaxf(mx0, __shfl_xor_sync(0xffffffffu, mx0, 1));
        mx0 = fmaxf(mx0, __shfl_xor_sync(0xffffffffu, mx0, 2));
        mx1 = fmaxf(mx1, __shfl_xor_sync(0xffffffffu, mx1, 1));
        mx1 = fmaxf(mx1, __shfl_xor_sync(0xffffffffu, mx1, 2));
        float mn0 = fmaxf(m0, mx0), mn1 = fmaxf(m1, mx1);
        float alpha0 = __expf(m0 - mn0), alpha1 = __expf(m1 - mn1);
        m0 = mn0; m1 = mn1;
        float s0 = 0.f, s1 = 0.f;
#pragma unroll
        for (int ni = 0; ni < 8; ni++) {
            sf[ni][0] = __expf(sf[ni][0] - mn0); s0 += sf[ni][0];
            sf[ni][1] = __expf(sf[ni][1] - mn0); s0 += sf[ni][1];
            sf[ni][2] = __expf(sf[ni][2] - mn1); s1 += sf[ni][2];
            sf[ni][3] = __expf(sf[ni][3] - mn1); s1 += sf[ni][3];
        }
        s0 += __shfl_xor_sync(0xffffffffu, s0, 1);
        s0 += __shfl_xor_sync(0xffffffffu, s0, 2);
        s1 += __shfl_xor_sync(0xffffffffu, s1, 1);
        s1 += __shfl_xor_sync(0xffffffffu, s1, 2);
        l0 = l0 * alpha0 + s0;
        l1 = l1 * alpha1 + s1;
#pragma unroll
        for (int ni = 0; ni < 8; ni++) {
            of[ni][0] *= alpha0; of[ni][1] *= alpha0;
            of[ni][2] *= alpha1; of[ni][3] *= alpha1;
        }

        // ---- P (tf32) into Ps; rows are warp-private -> syncwarp only ----
#pragma unroll
        for (int ni = 0; ni < 8; ni++) {
            int c = 8 * ni + 2 * tig;
            *(uint2*)&Ps[(q0w + gid) * KSR + c] =
                make_uint2(f2tf(sf[ni][0]), f2tf(sf[ni][1]));
            *(uint2*)&Ps[(q0w + gid + 8) * KSR + c] =
                make_uint2(f2tf(sf[ni][2]), f2tf(sf[ni][3]));
        }
        __syncwarp();

        // ---- O += P V ----
#pragma unroll
        for (int ks = 0; ks < 8; ks++) {
            uint32_t a[4];
            int r = (q0w + gid) * KSR + 8 * ks + tig;
            a[0] = Ps[r];
            a[1] = Ps[r + 8 * KSR];
            a[2] = Ps[r + 4];
            a[3] = Ps[r + 8 * KSR + 4];
#pragma unroll
            for (int ni = 0; ni < 8; ni++) {
                uint32_t b[2];
                int rv = (8 * ks + tig) * VSR + 8 * ni + gid;
                b[0] = Vc[rv];
                b[1] = Vc[rv + 4 * VSR];
                mma_tf32(of[ni], a, b);
            }
        }
    }

    // ---- epilogue: normalize, store y pre-rounded to tf32 ----
    float inv0 = 1.0f / l0, inv1 = 1.0f / l1;
    float* ybase = g_y + (size_t)(qb * 128 + q0w + gid) * DIM + h * HDIM;
#pragma unroll
    for (int ni = 0; ni < 8; ni++) {
        int c = 8 * ni + 2 * tig;
        *(uint2*)(ybase + c) =
            make_uint2(f2tf(of[ni][0] * inv0), f2tf(of[ni][1] * inv0));
        *(uint2*)(ybase + 8 * DIM + c) =
            make_uint2(f2tf(of[ni][2] * inv1), f2tf(of[ni][3] * inv1));
    }
}

// ---------------- launch ---------------------------------------------------
extern "C" void kernel_launch(void* const* d_in, const int* in_sizes, int n_in,
                              void* d_out, int out_size) {
    const float* x      = (const float*)d_in[0];
    const float* w_qkv  = (const float*)d_in[1];
    const float* w_proj = (const float*)d_in[2];
    const float* q_gain = (const float*)d_in[3];
    float* out = (float*)d_out;

    float *qkv_p, *y_p, *xr_p, *wq_p, *wp_p;
    cudaGetSymbolAddress((void**)&qkv_p, g_qkv);
    cudaGetSymbolAddress((void**)&y_p, g_y);
    cudaGetSymbolAddress((void**)&xr_p, g_xr);
    cudaGetSymbolAddress((void**)&wq_p, g_wq);
    cudaGetSymbolAddress((void**)&wp_p, g_wp);

    // pre-round inputs to tf32-in-f32
    round_kernel<<<1024, 256>>>(x, xr_p, TSEQ * DIM / 4);
    round_kernel<<<512, 256>>>(w_qkv, wq_p, QKVD * DIM / 4);
    round_kernel<<<512, 256>>>(w_proj, wp_p, DIM * DIM / 4);

    cudaFuncSetAttribute(gemm_tf32, cudaFuncAttributeMaxDynamicSharedMemorySize,
                         GEMM_SMEM_BYTES);
    gemm_tf32<<<dim3(QKVD / 128, TSEQ / 128), 256, GEMM_SMEM_BYTES>>>(
        xr_p, wq_p, qkv_p, TSEQ, QKVD, DIM);

    {
        int nwarps = TSEQ * (NH + 2 * NKV);
        prep_kernel<<<nwarps / 8, 256>>>(qkv_p, q_gain);
    }

    cudaFuncSetAttribute(attn_kernel, cudaFuncAttributeMaxDynamicSharedMemorySize,
                         ATTN_SMEM_BYTES);
    attn_kernel<<<dim3(TSEQ / 128, NH), 256, ATTN_SMEM_BYTES>>>();

    gemm_tf32<<<dim3(DIM / 128, TSEQ / 128), 256, GEMM_SMEM_BYTES>>>(
        y_p, wp_p, out, TSEQ, DIM, DIM);
}